// round 1
// baseline (speedup 1.0000x reference)
#include <cuda_runtime.h>
#include <cuda_bf16.h>

// Haar 2x2 DWT:
//   out[n][k*C + c][h2][w2], k in {0..3}
//   a = x[n][c][2h2][2w2],   b = x[n][c][2h2][2w2+1]
//   cc= x[n][c][2h2+1][2w2], d = x[n][c][2h2+1][2w2+1]
//   k0 = 0.5(a+b+cc+d); k1 = 0.5(a+b-cc-d); k2 = 0.5(a-b+cc-d); k3 = 0.5(a-b-cc+d)
//
// Shapes: x[16,64,256,256] f32 -> out[16,256,128,128] f32
// Each thread: 8 input cols x 2 rows (4x float4 loads), 4 output cols x 4 subbands
// (4x float4 stores). Fully coalesced 128-bit accesses both directions.

#define N_   16
#define C_   64
#define H_   256
#define W_   256
#define H2_  (H_/2)   // 128
#define W2_  (W_/2)   // 128
#define W4IN (W_/4)   // 64 float4 per input row
#define W4OUT (W2_/4) // 32 float4 per output row
#define TPATCH 32     // threads per (row-pair) covering W: W_/8 = 32

__global__ __launch_bounds__(256, 8)
void dwt2_haar_kernel(const float* __restrict__ x, float* __restrict__ out) {
    unsigned tid = blockIdx.x * blockDim.x + threadIdx.x;
    // decompose: tid = ((n*C_ + c)*H2_ + h2)*TPATCH + w8
    unsigned w8   = tid & (TPATCH - 1);
    unsigned rest = tid >> 5;            // log2(TPATCH)=5
    unsigned h2   = rest & (H2_ - 1);
    rest >>= 7;                          // log2(H2_)=7
    unsigned c    = rest & (C_ - 1);
    unsigned n    = rest >> 6;           // log2(C_)=6

    // input: two rows of this channel plane
    const float4* xv = (const float4*)x;
    unsigned row0 = ((n * C_ + c) * H_ + 2u * h2);      // row index (in rows of W_ floats)
    unsigned ib   = row0 * W4IN + w8 * 2u;              // float4 index

    float4 t0 = __ldg(&xv[ib]);
    float4 t1 = __ldg(&xv[ib + 1]);
    float4 b0 = __ldg(&xv[ib + W4IN]);
    float4 b1 = __ldg(&xv[ib + 1 + W4IN]);

    // 4 blocks: (t0.x,t0.y | b0.x,b0.y), (t0.z,t0.w | b0.z,b0.w),
    //           (t1.x,t1.y | b1.x,b1.y), (t1.z,t1.w | b1.z,b1.w)
    float4 o0, o1, o2, o3;  // subbands k=0..3, each holding 4 output cols

    {
        float a = t0.x, b = t0.y, cc = b0.x, d = b0.y;
        o0.x = 0.5f*(a+b+cc+d); o1.x = 0.5f*(a+b-cc-d);
        o2.x = 0.5f*(a-b+cc-d); o3.x = 0.5f*(a-b-cc+d);
    }
    {
        float a = t0.z, b = t0.w, cc = b0.z, d = b0.w;
        o0.y = 0.5f*(a+b+cc+d); o1.y = 0.5f*(a+b-cc-d);
        o2.y = 0.5f*(a-b+cc-d); o3.y = 0.5f*(a-b-cc+d);
    }
    {
        float a = t1.x, b = t1.y, cc = b1.x, d = b1.y;
        o0.z = 0.5f*(a+b+cc+d); o1.z = 0.5f*(a+b-cc-d);
        o2.z = 0.5f*(a-b+cc-d); o3.z = 0.5f*(a-b-cc+d);
    }
    {
        float a = t1.z, b = t1.w, cc = b1.z, d = b1.w;
        o0.w = 0.5f*(a+b+cc+d); o1.w = 0.5f*(a+b-cc-d);
        o2.w = 0.5f*(a-b+cc-d); o3.w = 0.5f*(a-b-cc+d);
    }

    // output: plane index for subband k is (n*4*C_ + k*C_ + c)
    float4* ov = (float4*)out;
    unsigned plane = n * (4u * C_) + c;                 // k=0 plane
    unsigned ob = (plane * H2_ + h2) * W4OUT + w8;      // float4 index
    const unsigned kstride = C_ * H2_ * W4OUT;          // per-subband plane stride in float4

    ov[ob]               = o0;
    ov[ob + kstride]     = o1;
    ov[ob + 2u*kstride]  = o2;
    ov[ob + 3u*kstride]  = o3;
}

extern "C" void kernel_launch(void* const* d_in, const int* in_sizes, int n_in,
                              void* d_out, int out_size) {
    const float* x = (const float*)d_in[0];
    float* out = (float*)d_out;
    // total threads = N_*C_*H2_*TPATCH = 16*64*128*32 = 4,194,304
    const unsigned total = N_ * C_ * H2_ * TPATCH;
    dwt2_haar_kernel<<<total / 256, 256>>>(x, out);
}